// round 9
// baseline (speedup 1.0000x reference)
#include <cuda_runtime.h>
#include <cuda_fp16.h>
#include <math.h>

#define BB 64
#define TT 2048
#define DD 128
#define UU 128
#define G3 384
#define NS 3

// ---------------- scratch (device globals: allocation-free) ----------------
__device__ float   g_GX[(size_t)TT * BB * G3];      // x@kernel + bias   [t][b][384]
__device__ float   g_PX[(size_t)TT * NS * BB * DD]; // x@sub_kernel_x    [t][r][128]
__device__ __half2 g_Rh2[64 * G3];                  // R packed: [ug][j], u=2ug,2ug+1
__device__ __half2 g_skh2[NS * 64 * 128];           // skh packed: [n][og][i]
__device__ __half2 g_dwh2[NS * 64 * 128];           // dw packed:  [n][ig][o]
__device__ __half2 g_awh2[192 * 128];               // aw packed:  [kg][j]

// ---------------- weight packing: reduction-major half2 --------------------
__global__ void pack_weights(const float* __restrict__ R,
                             const float* __restrict__ skh,
                             const float* __restrict__ dw,
                             const float* __restrict__ aw) {
    int idx = blockIdx.x * blockDim.x + threadIdx.x;
    if (idx < 24576) {                      // R: 64 x 384
        int ug = idx / G3, j = idx % G3;
        g_Rh2[idx] = __floats2half2_rn(R[(2*ug)*G3 + j], R[(2*ug+1)*G3 + j]);
    } else if (idx < 49152) {               // skh: 3 x 64 x 128
        int e = idx - 24576;
        int n = e / 8192, rem = e % 8192, og = rem / 128, i = rem % 128;
        const float* p = skh + n * 16384;
        g_skh2[e] = __floats2half2_rn(p[(2*og)*128 + i], p[(2*og+1)*128 + i]);
    } else if (idx < 73728) {               // dw: 3 x 64 x 128
        int e = idx - 49152;
        int n = e / 8192, rem = e % 8192, ig = rem / 128, o = rem % 128;
        const float* p = dw + n * 16384;
        g_dwh2[e] = __floats2half2_rn(p[(2*ig)*128 + o], p[(2*ig+1)*128 + o]);
    } else if (idx < 98304) {               // aw: 192 x 128
        int e = idx - 73728;
        int kg = e / 128, j = e % 128;
        g_awh2[e] = __floats2half2_rn(aw[(2*kg)*128 + j], aw[(2*kg+1)*128 + j]);
    }
}

// ---------------- parallel precompute of x-only terms (fp32) ---------------
__global__ void __launch_bounds__(256) precompute_kernel(
    const float* __restrict__ x, const float* __restrict__ K,
    const float* __restrict__ skx, const float* __restrict__ bias)
{
    __shared__ float4 xs4[BB * 32];                    // x[:,t,:] 64x128 = 32KB
    int t = blockIdx.x;
    int w = blockIdx.y;
    int tid = threadIdx.x;

    const float4* xg = (const float4*)x;
    #pragma unroll
    for (int q = tid; q < BB * 32; q += 256) {
        int bb = q >> 5, dq = q & 31;
        xs4[q] = xg[(size_t)(bb * TT + t) * 32 + dq];
    }
    __syncthreads();

    int jq = tid & 31;
    int bq = tid >> 5;
    int c  = 4 * jq;
    const float* xsf = (const float*)xs4;

    const float* W;
    int wstride;
    if (w < 3) { W = K + w * 128 + c; wstride = G3; }
    else       { W = skx + (w - 3) * 16384 + c; wstride = 128; }

    float acc[8][4];
    #pragma unroll
    for (int bi = 0; bi < 8; bi++)
        #pragma unroll
        for (int q = 0; q < 4; q++) acc[bi][q] = 0.f;

    #pragma unroll 4
    for (int d = 0; d < 128; d++) {
        float4 wv = *(const float4*)(W + (size_t)d * wstride);
        #pragma unroll
        for (int bi = 0; bi < 8; bi++) {
            float xv = xsf[(8 * bq + bi) * 128 + d];
            acc[bi][0] = fmaf(xv, wv.x, acc[bi][0]);
            acc[bi][1] = fmaf(xv, wv.y, acc[bi][1]);
            acc[bi][2] = fmaf(xv, wv.z, acc[bi][2]);
            acc[bi][3] = fmaf(xv, wv.w, acc[bi][3]);
        }
    }

    if (w < 3) {
        float4 bv = *(const float4*)(bias + w * 128 + c);
        #pragma unroll
        for (int bi = 0; bi < 8; bi++) {
            int b = 8 * bq + bi;
            float4 r = make_float4(acc[bi][0] + bv.x, acc[bi][1] + bv.y,
                                   acc[bi][2] + bv.z, acc[bi][3] + bv.w);
            *(float4*)&g_GX[((size_t)t * BB + b) * G3 + w * 128 + c] = r;
        }
    } else {
        #pragma unroll
        for (int bi = 0; bi < 8; bi++) {
            int b = 8 * bq + bi;
            *(float4*)&g_PX[((size_t)t * (NS * BB) + (w - 3) * BB + b) * 128 + c] =
                make_float4(acc[bi][0], acc[bi][1], acc[bi][2], acc[bi][3]);
        }
    }
}

// ---------------- sequential recurrence: 64 independent chains -------------
struct __align__(16) SeqSmem {
    __half2 dw[NS * 64 * 128];   // 98304 B
    __half2 aw[192 * 128];       // 98304 B
    __half2 h2[64];              // (h[2u],h[2u+1])
    __half2 s2[192];             // [k][og]
    __half2 agg2[192];           // [k][ig]
    __half2 sub2[192];           // [k][q]  (flat pairs)
    float   g[G3];
    float   part[G3];
};

__device__ __forceinline__ float sigm_fast(float v) {
    return __fdividef(1.f, 1.f + __expf(-v));
}
__device__ __forceinline__ float tanh_fast(float v) {
    return 1.f - __fdividef(2.f, __expf(2.f * v) + 1.f);
}
__device__ __forceinline__ __half2 h2_of(unsigned u) {
    return *reinterpret_cast<__half2*>(&u);
}

// 128-MAC dot: weights strided half2 stream, acts as 16 half2 via uint4 loads.
// fp16 pair accumulate, fold to fp32 every 8 HFMA2 (16 MACs).
template <int WS>
__device__ __forceinline__ float dot128(const __half2* __restrict__ w,
                                        const uint4* __restrict__ acts)
{
    float f0 = 0.f, f1 = 0.f;
    #pragma unroll
    for (int u8 = 0; u8 < 8; u8++) {
        uint4 A0 = acts[2 * u8];
        uint4 A1 = acts[2 * u8 + 1];
        const __half2* wp = w + (size_t)(u8 * 8) * WS;
        __half2 acc = __hmul2(wp[0], h2_of(A0.x));
        acc = __hfma2(wp[1 * WS], h2_of(A0.y), acc);
        acc = __hfma2(wp[2 * WS], h2_of(A0.z), acc);
        acc = __hfma2(wp[3 * WS], h2_of(A0.w), acc);
        acc = __hfma2(wp[4 * WS], h2_of(A1.x), acc);
        acc = __hfma2(wp[5 * WS], h2_of(A1.y), acc);
        acc = __hfma2(wp[6 * WS], h2_of(A1.z), acc);
        acc = __hfma2(wp[7 * WS], h2_of(A1.w), acc);
        float2 ff = __half22float2(acc);
        f0 += ff.x;
        f1 += ff.y;
    }
    return f0 + f1;
}

__global__ void __launch_bounds__(384, 1) seq_kernel(
    const float* __restrict__ stk, const float* __restrict__ db,
    const float* __restrict__ ab, float* __restrict__ out)
{
    extern __shared__ char smem_raw[];
    SeqSmem& sh = *reinterpret_cast<SeqSmem*>(smem_raw);

    int tid = threadIdx.x;
    int b   = blockIdx.x;
    int k   = tid >> 7;                 // 0..2
    int col = tid & 127;
    int r   = 3 * b + k;                // owned row in (n*64+b2) space
    int n   = r >> 6;                   // sub-layer index (fixed over time)

    // bulk-copy SMEM-resident weights
    {
        const uint4* src_dw = (const uint4*)g_dwh2;
        const uint4* src_aw = (const uint4*)g_awh2;
        uint4* dst_dw = (uint4*)sh.dw;
        uint4* dst_aw = (uint4*)sh.aw;
        for (int i = tid; i < 24576 / 4; i += 384) {
            dst_dw[i] = src_dw[i];
            dst_aw[i] = src_aw[i];
        }
    }
    // per-thread constants in registers
    float db_r = db[n * 128 + col];
    float rh_r = stk[n * 256 + col];
    float rx_r = stk[n * 256 + 128 + col];
    float ab_r = (tid < 128) ? ab[tid] : 0.f;
    float s_reg = 0.f, c_reg = 0.f, tc = 0.f;

    // zero initial state mirrors
    if (tid < 64)  sh.h2[tid] = __float2half2_rn(0.f);
    if (tid < 192) sh.s2[tid] = __float2half2_rn(0.f);
    __syncthreads();

    const __half2* Rp = g_Rh2 + tid;                 // stride G3
    const __half2* Sp = g_skh2 + n * 8192 + col;     // stride 128
    const __half2* Dp = sh.dw  + n * 8192 + col;     // stride 128 (SMEM)
    const __half2* Ap = sh.aw  + (k << 13) + col;    // stride 128 (SMEM), kg0=64k
    const uint4* hq = (const uint4*)sh.h2;
    const uint4* sq = (const uint4*)(sh.s2  + (k << 6));
    const uint4* aq = (const uint4*)(sh.agg2 + (k << 6));
    const uint4* bq = (const uint4*)(sh.sub2 + (k << 6));

    const float* gxp = g_GX + (size_t)b * G3 + tid;
    const float* pxp = g_PX + (size_t)r * 128 + col;
    float gx = __ldcs(gxp);
    float px = __ldcs(pxp);

    int q   = col >> 1;        // pair index within 64
    bool wr = !(col & 1);      // even-lane writer

    for (int t = 0; t < TT; t++) {
        int tn = (t + 1 < TT) ? (t + 1) : t;
        float gxN = __ldcs(gxp + (size_t)tn * (BB * G3));
        float pxN = __ldcs(pxp + (size_t)tn * (NS * BB * 128));

        // ---- stage 1 (gates) + stage 2 (agg_in): read prev-step h2, s2
        float gdot = dot128<G3>(Rp, hq);
        float edot = dot128<128>(Sp, sq);
        sh.g[tid] = sigm_fast(gx + gdot);
        float aggv = px + edot;
        float aggp = __shfl_xor_sync(0xffffffffu, aggv, 1);
        if (wr) sh.agg2[(k << 6) + q] = __floats2half2_rn(aggv, aggp);
        __syncthreads();

        // ---- stage 3 (dense + relu, s update, c update)
        float ddot = dot128<128>(Dp, aq);
        float so = fmaxf(ddot + db_r, 0.f);
        s_reg = fmaf(rh_r, so, rx_r * s_reg);
        float sop = __shfl_xor_sync(0xffffffffu, so, 1);
        float ssp = __shfl_xor_sync(0xffffffffu, s_reg, 1);
        if (wr) {
            sh.sub2[(k << 6) + q] = __floats2half2_rn(so, sop);
            sh.s2[(k << 6) + q]   = __floats2half2_rn(s_reg, ssp);
        }
        if (tid < 128) {
            c_reg = fmaf(sh.g[128 + tid], c_reg, sh.g[tid] * tanh_fast(sh.g[256 + tid]));
            tc = tanh_fast(c_reg);
        }
        __syncthreads();

        // ---- stage 4a: split-K over flat(sub) @ agg_w (all threads)
        sh.part[tid] = dot128<128>(Ap, bq);
        __syncthreads();

        // ---- stage 4b: combine partials, output gate, h update
        if (tid < 128) {
            float p = sh.part[tid] + sh.part[128 + tid] + sh.part[256 + tid];
            float ov = sigm_fast(p + ab_r);
            float hv = ov * tc;
            float hp = __shfl_xor_sync(0xffffffffu, hv, 1);
            if (wr) sh.h2[q] = __floats2half2_rn(hv, hp);
            __stcs(&out[((size_t)b * TT + t) * 128 + tid], hv);  // (B,T,U)
        }
        gx = gxN;
        px = pxN;
        __syncthreads();
    }
}

// ---------------- launch ----------------------------------------------------
extern "C" void kernel_launch(void* const* d_in, const int* in_sizes, int n_in,
                              void* d_out, int out_size)
{
    const float* x    = (const float*)d_in[0];
    const float* K    = (const float*)d_in[1];
    const float* R    = (const float*)d_in[2];
    const float* bias = (const float*)d_in[3];
    const float* skx  = (const float*)d_in[4];
    const float* skh  = (const float*)d_in[5];
    const float* stk  = (const float*)d_in[6];
    const float* dw   = (const float*)d_in[7];
    const float* db   = (const float*)d_in[8];
    const float* aw   = (const float*)d_in[9];
    const float* ab   = (const float*)d_in[10];
    float* out = (float*)d_out;

    pack_weights<<<384, 256>>>(R, skh, dw, aw);

    dim3 pg(TT, 6);
    precompute_kernel<<<pg, 256>>>(x, K, skx, bias);

    cudaFuncSetAttribute(seq_kernel, cudaFuncAttributeMaxDynamicSharedMemorySize,
                         (int)sizeof(SeqSmem));
    seq_kernel<<<BB, 384, sizeof(SeqSmem)>>>(stk, db, ab, out);
}

// round 10
// speedup vs baseline: 1.4876x; 1.4876x over previous
#include <cuda_runtime.h>
#include <cuda_fp16.h>
#include <math.h>

#define BB 64
#define TT 2048
#define DD 128
#define UU 128
#define G3 384
#define NS 3

// ---------------- scratch (device globals: allocation-free) ----------------
__device__ float   g_GX[(size_t)TT * BB * G3];      // x@kernel + bias   [t][b][384]
__device__ float   g_PX[(size_t)TT * NS * BB * DD]; // x@sub_kernel_x    [t][r][128]
__device__ __half2 g_Rh2[64 * G3];                  // R packed: [ug][j]
__device__ __half2 g_skh2[NS * 64 * 128];           // skh packed: [n][og][i]
__device__ __half2 g_dwh2[NS * 64 * 128];           // dw packed:  [n][ig][o]
__device__ __half2 g_awh2[192 * 128];               // aw packed:  [kg][j]

// ---------------- weight packing: reduction-major half2 --------------------
__global__ void pack_weights(const float* __restrict__ R,
                             const float* __restrict__ skh,
                             const float* __restrict__ dw,
                             const float* __restrict__ aw) {
    int idx = blockIdx.x * blockDim.x + threadIdx.x;
    if (idx < 24576) {                      // R: 64 x 384
        int ug = idx / G3, j = idx % G3;
        g_Rh2[idx] = __floats2half2_rn(R[(2*ug)*G3 + j], R[(2*ug+1)*G3 + j]);
    } else if (idx < 49152) {               // skh: 3 x 64 x 128
        int e = idx - 24576;
        int n = e / 8192, rem = e % 8192, og = rem / 128, i = rem % 128;
        const float* p = skh + n * 16384;
        g_skh2[e] = __floats2half2_rn(p[(2*og)*128 + i], p[(2*og+1)*128 + i]);
    } else if (idx < 73728) {               // dw: 3 x 64 x 128
        int e = idx - 49152;
        int n = e / 8192, rem = e % 8192, ig = rem / 128, o = rem % 128;
        const float* p = dw + n * 16384;
        g_dwh2[e] = __floats2half2_rn(p[(2*ig)*128 + o], p[(2*ig+1)*128 + o]);
    } else if (idx < 98304) {               // aw: 192 x 128
        int e = idx - 73728;
        int kg = e / 128, j = e % 128;
        g_awh2[e] = __floats2half2_rn(aw[(2*kg)*128 + j], aw[(2*kg+1)*128 + j]);
    }
}

// ---------------- parallel precompute of x-only terms (fp32) ---------------
__global__ void __launch_bounds__(256) precompute_kernel(
    const float* __restrict__ x, const float* __restrict__ K,
    const float* __restrict__ skx, const float* __restrict__ bias)
{
    __shared__ float4 xs4[BB * 32];                    // x[:,t,:] 64x128 = 32KB
    int t = blockIdx.x;
    int w = blockIdx.y;
    int tid = threadIdx.x;

    const float4* xg = (const float4*)x;
    #pragma unroll
    for (int q = tid; q < BB * 32; q += 256) {
        int bb = q >> 5, dq = q & 31;
        xs4[q] = xg[(size_t)(bb * TT + t) * 32 + dq];
    }
    __syncthreads();

    int jq = tid & 31;
    int bq = tid >> 5;
    int c  = 4 * jq;
    const float* xsf = (const float*)xs4;

    const float* W;
    int wstride;
    if (w < 3) { W = K + w * 128 + c; wstride = G3; }
    else       { W = skx + (w - 3) * 16384 + c; wstride = 128; }

    float acc[8][4];
    #pragma unroll
    for (int bi = 0; bi < 8; bi++)
        #pragma unroll
        for (int q = 0; q < 4; q++) acc[bi][q] = 0.f;

    #pragma unroll 4
    for (int d = 0; d < 128; d++) {
        float4 wv = *(const float4*)(W + (size_t)d * wstride);
        #pragma unroll
        for (int bi = 0; bi < 8; bi++) {
            float xv = xsf[(8 * bq + bi) * 128 + d];
            acc[bi][0] = fmaf(xv, wv.x, acc[bi][0]);
            acc[bi][1] = fmaf(xv, wv.y, acc[bi][1]);
            acc[bi][2] = fmaf(xv, wv.z, acc[bi][2]);
            acc[bi][3] = fmaf(xv, wv.w, acc[bi][3]);
        }
    }

    if (w < 3) {
        float4 bv = *(const float4*)(bias + w * 128 + c);
        #pragma unroll
        for (int bi = 0; bi < 8; bi++) {
            int b = 8 * bq + bi;
            float4 r = make_float4(acc[bi][0] + bv.x, acc[bi][1] + bv.y,
                                   acc[bi][2] + bv.z, acc[bi][3] + bv.w);
            *(float4*)&g_GX[((size_t)t * BB + b) * G3 + w * 128 + c] = r;
        }
    } else {
        #pragma unroll
        for (int bi = 0; bi < 8; bi++) {
            int b = 8 * bq + bi;
            *(float4*)&g_PX[((size_t)t * (NS * BB) + (w - 3) * BB + b) * 128 + c] =
                make_float4(acc[bi][0], acc[bi][1], acc[bi][2], acc[bi][3]);
        }
    }
}

// ---------------- sequential recurrence: 64 independent chains -------------
struct __align__(16) SeqSmem {
    __half2 dw[NS * 64 * 128];   // 98304 B
    __half2 aw[192 * 128];       // 98304 B
    __half2 h2[64];
    __half2 s2[192];
    __half2 agg2[192];
    __half2 sub2[192];
    float   g[G3];
    float   pB[768];
    float   pC[768];
};

__device__ __forceinline__ float sigm_fast(float v) {
    return __fdividef(1.f, 1.f + __expf(-v));
}
__device__ __forceinline__ float tanh_fast(float v) {
    return 1.f - __fdividef(2.f, __expf(2.f * v) + 1.f);
}
__device__ __forceinline__ __half2 h2_of(unsigned u) {
    return *reinterpret_cast<__half2*>(&u);
}

// 128-MAC dot: 4 independent half2 chains, folded to fp32 every 16 MACs.
template <int WS, int NBLK>
__device__ __forceinline__ float dot_h2(const __half2* __restrict__ w,
                                        const uint4* __restrict__ acts)
{
    float f0 = 0.f, f1 = 0.f;
    #pragma unroll
    for (int blk = 0; blk < NBLK; blk++) {
        __half2 z = __float2half2_rn(0.f);
        __half2 c0 = z, c1 = z, c2 = z, c3 = z;
        #pragma unroll
        for (int i = 0; i < 4; i++) {
            uint4 A = acts[4 * blk + i];
            const __half2* wp = w + (size_t)(16 * blk + 4 * i) * WS;
            c0 = __hfma2(wp[0],      h2_of(A.x), c0);
            c1 = __hfma2(wp[1 * WS], h2_of(A.y), c1);
            c2 = __hfma2(wp[2 * WS], h2_of(A.z), c2);
            c3 = __hfma2(wp[3 * WS], h2_of(A.w), c3);
        }
        __half2 sc = __hadd2(__hadd2(c0, c1), __hadd2(c2, c3));
        float2 ff = __half22float2(sc);
        f0 += ff.x;
        f1 += ff.y;
    }
    return f0 + f1;
}

__global__ void __launch_bounds__(768, 1) seq_kernel(
    const float* __restrict__ stk, const float* __restrict__ db,
    const float* __restrict__ ab, float* __restrict__ out)
{
    extern __shared__ char smem_raw[];
    SeqSmem& sh = *reinterpret_cast<SeqSmem*>(smem_raw);

    int tid  = threadIdx.x;
    int b    = blockIdx.x;
    int grp  = tid >> 8 >> 1;           // tid/512? no — compute directly below
    grp = tid / 384;                    // 0: gates/partial0, 1: agg/partial1
    int t384 = tid - grp * 384;
    int k    = t384 >> 7;               // 0..2
    int col  = t384 & 127;
    int r    = 3 * b + k;               // row in (n*64+b2) space
    int n    = r >> 6;                  // sub-layer index

    // bulk-copy SMEM-resident weights (dw, aw)
    {
        const uint4* src_dw = (const uint4*)g_dwh2;
        const uint4* src_aw = (const uint4*)g_awh2;
        uint4* dst_dw = (uint4*)sh.dw;
        uint4* dst_aw = (uint4*)sh.aw;
        for (int i = tid; i < 6144; i += 768) {
            dst_dw[i] = src_dw[i];
            dst_aw[i] = src_aw[i];
        }
    }
    // per-thread constants (meaningful on tid<384 / tid<128)
    float db_r = (tid < 384) ? db[n * 128 + col] : 0.f;
    float rh_r = (tid < 384) ? stk[n * 256 + col] : 0.f;
    float rx_r = (tid < 384) ? stk[n * 256 + 128 + col] : 0.f;
    float ab_r = (tid < 128) ? ab[tid] : 0.f;
    float s_reg = 0.f, c_reg = 0.f, tc = 0.f;

    if (tid < 64)  sh.h2[tid] = __float2half2_rn(0.f);
    if (tid < 192) sh.s2[tid] = __float2half2_rn(0.f);
    __syncthreads();

    // stage-A weight pointers
    const __half2* Rp = g_Rh2 + t384;              // gates (grp0), stride G3
    const __half2* Sp = g_skh2 + n * 8192 + col;   // agg   (grp1), stride 128
    // stage-B weights (SMEM): output t384, reduction half grp
    const __half2* Dp = sh.dw + n * 8192 + (grp * 32) * 128 + col;
    // stage-C weights (SMEM): output j=tid&127, sixth p=tid>>7
    int pC6 = tid >> 7;                 // 0..5
    int jC  = tid & 127;
    const __half2* Ap = sh.aw + (pC6 * 32) * 128 + jC;

    // x-term stream (stride per t is 24576 floats for both arrays)
    const float* xp = (grp == 0) ? (g_GX + (size_t)b * G3 + t384)
                                 : (g_PX + (size_t)r * 128 + col);
    float xt = __ldcs(xp);

    const uint4* hq = (const uint4*)sh.h2;
    const uint4* sq = (const uint4*)(sh.s2 + (k << 6));
    const uint4* aqB = (const uint4*)(sh.agg2 + (k << 6)) + 8 * grp;
    const uint4* bqC = (const uint4*)sh.sub2 + 8 * pC6;

    for (int t = 0; t < TT; t++) {
        int tn = (t + 1 < TT) ? (t + 1) : t;
        float xtN = __ldcs(xp + (size_t)tn * 24576);

        // ---- stage A: gates (warps 0-11) || agg_in (warps 12-23)
        if (grp == 0) {
            float gdot = dot_h2<G3, 4>(Rp, hq);
            sh.g[t384] = sigm_fast(xt + gdot);
        } else {
            float edot = dot_h2<128, 4>(Sp, sq);
            float aggv = xt + edot;
            float aggp = __shfl_xor_sync(0xffffffffu, aggv, 1);
            if (!(col & 1))
                sh.agg2[(k << 6) + (col >> 1)] = __floats2half2_rn(aggv, aggp);
        }
        __syncthreads();

        // ---- stage B: dense partials (2-way split-K, all 768 threads)
        sh.pB[tid] = dot_h2<128, 2>(Dp, aqB);
        __syncthreads();

        // ---- stage B2: combine, relu, s update, c update (384 threads)
        if (tid < 384) {
            float so = fmaxf(sh.pB[tid] + sh.pB[tid + 384] + db_r, 0.f);
            s_reg = fmaf(rh_r, so, rx_r * s_reg);
            float sop = __shfl_xor_sync(0xffffffffu, so, 1);
            float ssp = __shfl_xor_sync(0xffffffffu, s_reg, 1);
            if (!(col & 1)) {
                sh.sub2[(k << 6) + (col >> 1)] = __floats2half2_rn(so, sop);
                sh.s2[(k << 6) + (col >> 1)]   = __floats2half2_rn(s_reg, ssp);
            }
            if (tid < 128) {
                c_reg = fmaf(sh.g[128 + tid], c_reg,
                             sh.g[tid] * tanh_fast(sh.g[256 + tid]));
                tc = tanh_fast(c_reg);
            }
        }
        __syncthreads();

        // ---- stage C: agg_w partials (6-way split-K, all 768 threads)
        sh.pC[tid] = dot_h2<128, 2>(Ap, bqC);
        __syncthreads();

        // ---- stage D: combine, output gate, h update (128 threads)
        if (tid < 128) {
            float pv = ((sh.pC[tid]       + sh.pC[tid + 128]) +
                        (sh.pC[tid + 256] + sh.pC[tid + 384])) +
                       (sh.pC[tid + 512] + sh.pC[tid + 640]);
            float ov = sigm_fast(pv + ab_r);
            float hv = ov * tc;
            float hp = __shfl_xor_sync(0xffffffffu, hv, 1);
            if (!(tid & 1)) sh.h2[tid >> 1] = __floats2half2_rn(hv, hp);
            __stcs(&out[((size_t)b * TT + t) * 128 + tid], hv);  // (B,T,U)
        }
        xt = xtN;
        __syncthreads();
    }
}

// ---------------- launch ----------------------------------------------------
extern "C" void kernel_launch(void* const* d_in, const int* in_sizes, int n_in,
                              void* d_out, int out_size)
{
    const float* x    = (const float*)d_in[0];
    const float* K    = (const float*)d_in[1];
    const float* R    = (const float*)d_in[2];
    const float* bias = (const float*)d_in[3];
    const float* skx  = (const float*)d_in[4];
    const float* skh  = (const float*)d_in[5];
    const float* stk  = (const float*)d_in[6];
    const float* dw   = (const float*)d_in[7];
    const float* db   = (const float*)d_in[8];
    const float* aw   = (const float*)d_in[9];
    const float* ab   = (const float*)d_in[10];
    float* out = (float*)d_out;

    pack_weights<<<384, 256>>>(R, skh, dw, aw);

    dim3 pg(TT, 6);
    precompute_kernel<<<pg, 256>>>(x, K, skx, bias);

    cudaFuncSetAttribute(seq_kernel, cudaFuncAttributeMaxDynamicSharedMemorySize,
                         (int)sizeof(SeqSmem));
    seq_kernel<<<BB, 768, sizeof(SeqSmem)>>>(stk, db, ab, out);
}